// round 7
// baseline (speedup 1.0000x reference)
#include <cuda_runtime.h>

// Problem constants
#define T_STEPS 512
#define NBATCH  512
#define IN_DIM  64
#define H       100

// Layer-1 concatenated input [x(64) | h1(100) | pad] -> 176, quarters of 44 (11 float4)
// Layer-2 concatenated input [h1(100) | h2(100) | pad] -> 208, quarters of 52 (13 float4)
#define L1_LEN  176
#define L2_LEN  208
#define L1_Q    44
#define L2_Q    52
#define NQ1     11      // float4 chunks per quarter, layer 1
#define NQ2     13      // float4 chunks per quarter, layer 2

#define ROWS     4      // batch rows per CTA
#define NCTA     128    // 128 * 4 = 512 rows
#define NTHREADS 832    // 26 warps: 13 warps L1 (400 active), 13 warps L2 (400 active)
#define L2_BASE  416

// Transposed + concatenated + zero-padded weights (quarter-major, same as smem read order)
__device__ float g_W1T[H * L1_LEN];
__device__ float g_W2T[H * L2_LEN];

__global__ void prep_kernel(const float* __restrict__ W1x, const float* __restrict__ W1h,
                            const float* __restrict__ W2x, const float* __restrict__ W2h) {
    int idx = blockIdx.x * blockDim.x + threadIdx.x;
    const int n1 = H * L1_LEN;
    if (idx < n1) {
        int j = idx / L1_LEN, k = idx % L1_LEN;
        float v = 0.0f;
        if (k < IN_DIM)           v = W1x[k * H + j];
        else if (k < IN_DIM + H)  v = W1h[(k - IN_DIM) * H + j];
        g_W1T[idx] = v;
    } else {
        int i2 = idx - n1;
        if (i2 < H * L2_LEN) {
            int j = i2 / L2_LEN, k = i2 % L2_LEN;
            float v = 0.0f;
            if (k < H)            v = W2x[k * H + j];
            else if (k < 2 * H)   v = W2h[(k - H) * H + j];
            g_W2T[i2] = v;
        }
    }
}

// Accurate fast tanh: 1 - 2/(exp(2x)+1).  __expf = MUFU.EX2 path, rel err ~1e-6.
__device__ __forceinline__ float fast_tanh(float x) {
    float e = __expf(2.0f * x);
    return 1.0f - __fdividef(2.0f, e + 1.0f);
}

// Packed fp32 FMA (sm_103a FFMA2): acc = a*b + acc, two lanes at once.
__device__ __forceinline__ void ffma2(unsigned long long& acc,
                                      unsigned long long a, unsigned long long b) {
    asm("fma.rn.f32x2 %0, %1, %2, %0;" : "+l"(acc) : "l"(a), "l"(b));
}

// Permuted smem position for logical concat-index k (QLEN = quarter length in floats):
//   quarter q = k / QLEN, w = k % QLEN, pos = (w/4)*16 + q*4 + (w%4)
__device__ __forceinline__ int perm_pos(int k, int qlen) {
    int q = k / qlen, w = k - q * qlen;
    return (w >> 2) * 16 + q * 4 + (w & 3);
}

__global__ void __launch_bounds__(NTHREADS, 1)
rnn_kernel(const float* __restrict__ x,
           const float* __restrict__ b1, const float* __restrict__ b2,
           const float* __restrict__ Wo, const float* __restrict__ bo,
           float* __restrict__ out) {
    // Double-buffered per-row input vectors, QUARTER-INTERLEAVED at float4 grain:
    // float4 slot (i*4 + q) holds chunk i of quarter q. A warp's simultaneous
    // reads (q = lane&3, same i) span one contiguous 64B line -> 1 LDS wavefront.
    __shared__ __align__(128) float s_in1[2][ROWS][L1_LEN];
    __shared__ __align__(128) float s_in2[2][ROWS][L2_LEN];

    const int t  = threadIdx.x;
    const int b0 = blockIdx.x * ROWS;

    // Zero both buffers (pads stay 0 forever; h(-1)=0, h2(-2)=0).
    for (int i = t; i < 2 * ROWS * L1_LEN; i += NTHREADS) ((float*)s_in1)[i] = 0.0f;
    for (int i = t; i < 2 * ROWS * L2_LEN; i += NTHREADS) ((float*)s_in2)[i] = 0.0f;

    const bool isL1 = (t < L2_BASE);
    const float4* __restrict__ xg4 = (const float4*)x;
    const int pre_r = (t >> 4) & 3;   // x-prefetch mapping: 64 threads = 4 rows x 16 float4
    const int pre_d = t & 15;
    // Permuted float4 slot for x chunk pre_d (k = 4*pre_d, quarters of 44):
    const int pre_qx   = (pre_d >= NQ1) ? 1 : 0;
    const int pre_pos4 = (pre_d - pre_qx * NQ1) * 4 + pre_qx;

    // Load this thread's weight slice into registers as f32x2 pairs.
    unsigned long long w2a[NQ2], w2b[NQ2];   // pair0 / pair1 of each float4 chunk
    float biasv = 0.0f;
    int jw, q;
    int pos_h1 = 0, pos_h1b = 0, pos_h2 = 0;  // permuted scalar store slots
    if (isL1) {
        jw = t >> 2; q = t & 3;
        int jc = jw < H ? jw : H - 1;
        const ulonglong2* wsrc = ((const ulonglong2*)g_W1T) + jc * (L1_LEN / 4) + q * NQ1;
        #pragma unroll
        for (int i = 0; i < NQ1; ++i) { ulonglong2 wv = wsrc[i]; w2a[i] = wv.x; w2b[i] = wv.y; }
        biasv = b1[jc];
        pos_h1  = perm_pos(IN_DIM + jc, L1_Q);  // h1 into next s_in1
        pos_h1b = perm_pos(jc,          L2_Q);  // h1 into next s_in2
    } else {
        int u = t - L2_BASE;
        jw = u >> 2; q = u & 3;
        int jc = jw < H ? jw : H - 1;
        const ulonglong2* wsrc = ((const ulonglong2*)g_W2T) + jc * (L2_LEN / 4) + q * NQ2;
        #pragma unroll
        for (int i = 0; i < NQ2; ++i) { ulonglong2 wv = wsrc[i]; w2a[i] = wv.x; w2b[i] = wv.y; }
        biasv = b2[jc];
        pos_h2  = perm_pos(H + jc, L2_Q);       // h2 into next s_in2
    }

    __syncthreads();   // zero-fill visible before x(0) staging

    // Stage x(0) into buffer 0 (permuted slots).
    if (t < 64) {
        float4 v = xg4[(b0 + pre_r) * (T_STEPS * (IN_DIM / 4)) + pre_d];
        ((float4*)&s_in1[0][pre_r][0])[pre_pos4] = v;
    }
    __syncthreads();

    // Pipelined phases: at phase p, L1 computes h1(p) (p<T), L2 computes h2(p-1) (p>=1).
    // Reads from buf (p&1), writes to buf (p&1)^1; one barrier per phase.
    for (int p = 0; p <= T_STEPS; ++p) {
        const int pb = p & 1;

        // Prefetch x(p+1) (issued early, stored after compute).
        float4 xpre;
        const bool doPre = isL1 && (t < 64) && (p + 1 < T_STEPS);
        if (doPre)
            xpre = xg4[(b0 + pre_r) * (T_STEPS * (IN_DIM / 4)) + (p + 1) * (IN_DIM / 4) + pre_d];

        if (isL1) {
            if (p < T_STEPS) {
                #pragma unroll
                for (int r = 0; r < ROWS; ++r) {
                    const ulonglong2* v = ((const ulonglong2*)&s_in1[pb][r][0]) + q;
                    unsigned long long a0 = 0ull, a1 = 0ull;
                    #pragma unroll
                    for (int i = 0; i < NQ1; ++i) {
                        ulonglong2 vv = v[i * 4];
                        ffma2(a0, w2a[i], vv.x);
                        ffma2(a1, w2b[i], vv.y);
                    }
                    unsigned long long as;
                    asm("add.rn.f32x2 %0, %1, %2;" : "=l"(as) : "l"(a0), "l"(a1));
                    float lo, hi;
                    asm("mov.b64 {%0, %1}, %2;" : "=f"(lo), "=f"(hi) : "l"(as));
                    float red = lo + hi;
                    red += __shfl_xor_sync(0xffffffffu, red, 1);
                    red += __shfl_xor_sync(0xffffffffu, red, 2);
                    if (q == 0 && jw < H) {
                        float h = fast_tanh(red + biasv);
                        s_in1[pb ^ 1][r][pos_h1]  = h;   // next L1's h1(t-1)
                        s_in2[pb ^ 1][r][pos_h1b] = h;   // next L2's h1(t-1)
                        if (p == T_STEPS - 1)
                            out[NBATCH + (b0 + r) * H + jw] = h;   // h1_T
                    }
                }
            }
        } else {
            if (p >= 1) {
                #pragma unroll
                for (int r = 0; r < ROWS; ++r) {
                    const ulonglong2* v = ((const ulonglong2*)&s_in2[pb][r][0]) + q;
                    unsigned long long a0 = 0ull, a1 = 0ull;
                    #pragma unroll
                    for (int i = 0; i < NQ2; ++i) {
                        ulonglong2 vv = v[i * 4];
                        ffma2(a0, w2a[i], vv.x);
                        ffma2(a1, w2b[i], vv.y);
                    }
                    unsigned long long as;
                    asm("add.rn.f32x2 %0, %1, %2;" : "=l"(as) : "l"(a0), "l"(a1));
                    float lo, hi;
                    asm("mov.b64 {%0, %1}, %2;" : "=f"(lo), "=f"(hi) : "l"(as));
                    float red = lo + hi;
                    red += __shfl_xor_sync(0xffffffffu, red, 1);
                    red += __shfl_xor_sync(0xffffffffu, red, 2);
                    if (q == 0 && jw < H) {
                        float h = fast_tanh(red + biasv);
                        s_in2[pb ^ 1][r][pos_h2] = h;    // next L2's h2(t-1)
                        if (p == T_STEPS)
                            out[NBATCH + NBATCH * H + (b0 + r) * H + jw] = h;   // h2_T
                    }
                }
            }
        }

        if (doPre)
            ((float4*)&s_in1[pb ^ 1][pre_r][0])[pre_pos4] = xpre;

        __syncthreads();
    }

    // out = h2_T @ Wo + bo.  h2(T-1) was written at phase 512 (pb=0) into buffer 1.
    if (t < ROWS) {
        float acc = bo[0];
        #pragma unroll 4
        for (int k = 0; k < H; ++k)
            acc = fmaf(s_in2[1][t][perm_pos(H + k, L2_Q)], Wo[k], acc);
        out[b0 + t] = acc;
    }
}

extern "C" void kernel_launch(void* const* d_in, const int* in_sizes, int n_in,
                              void* d_out, int out_size) {
    const float* x   = (const float*)d_in[0];
    const float* W1x = (const float*)d_in[1];
    const float* W1h = (const float*)d_in[2];
    const float* b1  = (const float*)d_in[3];
    const float* W2x = (const float*)d_in[4];
    const float* W2h = (const float*)d_in[5];
    const float* b2  = (const float*)d_in[6];
    const float* Wo  = (const float*)d_in[7];
    const float* bo  = (const float*)d_in[8];
    float* out = (float*)d_out;

    // Build transposed/padded weight images (38400 elements total).
    prep_kernel<<<150, 256>>>(W1x, W1h, W2x, W2h);

    // Persistent batch-partitioned RNN: 128 CTAs x 4 rows, no inter-CTA sync.
    rnn_kernel<<<NCTA, NTHREADS>>>(x, b1, b2, Wo, bo, out);
}

// round 8
// speedup vs baseline: 1.6460x; 1.6460x over previous
#include <cuda_runtime.h>

// Problem constants
#define T_STEPS 512
#define NBATCH  512
#define IN_DIM  64
#define H       100

// Layer-1 concatenated input [x(64) | h1(100) | pad(12)] -> 176, chunks of 22
// Layer-2 concatenated input [h1(100) | h2(100) | pad(8)] -> 208, chunks of 26
#define L1_LEN  176
#define L2_LEN  208
#define KC1     22      // 176 / 8
#define KC2     26      // 208 / 8

#define ROWS     4      // batch rows per CTA
#define NCTA     128    // 128 * 4 = 512 rows
#define NTHREADS 832    // 26 warps: 13 L1 + 13 L2 (416 threads each, 400 needed)
#define L2_BASE  416

// Transposed + concatenated + zero-padded weights: [col j][k] row-major per col
__device__ float g_W1T[H * L1_LEN];
__device__ float g_W2T[H * L2_LEN];

__global__ void prep_kernel(const float* __restrict__ W1x, const float* __restrict__ W1h,
                            const float* __restrict__ W2x, const float* __restrict__ W2h) {
    int idx = blockIdx.x * blockDim.x + threadIdx.x;
    const int n1 = H * L1_LEN;
    if (idx < n1) {
        int j = idx / L1_LEN, k = idx % L1_LEN;
        float v = 0.0f;
        if (k < IN_DIM)           v = W1x[k * H + j];
        else if (k < IN_DIM + H)  v = W1h[(k - IN_DIM) * H + j];
        g_W1T[idx] = v;
    } else {
        int i2 = idx - n1;
        if (i2 < H * L2_LEN) {
            int j = i2 / L2_LEN, k = i2 % L2_LEN;
            float v = 0.0f;
            if (k < H)            v = W2x[k * H + j];
            else if (k < 2 * H)   v = W2h[(k - H) * H + j];
            g_W2T[i2] = v;
        }
    }
}

// Accurate fast tanh: 1 - 2/(exp(2x)+1).  __expf = MUFU.EX2 path, rel err ~1e-6.
__device__ __forceinline__ float fast_tanh(float x) {
    float e = __expf(2.0f * x);
    return 1.0f - __fdividef(2.0f, e + 1.0f);
}

__global__ void __launch_bounds__(NTHREADS, 1)
rnn_kernel(const float* __restrict__ x,
           const float* __restrict__ b1, const float* __restrict__ b2,
           const float* __restrict__ Wo, const float* __restrict__ bo,
           float* __restrict__ out) {
    // Double-buffered per-row input vectors (plain k-order).
    __shared__ __align__(16) float s_in1[2][ROWS][L1_LEN];
    __shared__ __align__(16) float s_in2[2][ROWS][L2_LEN];

    const int t  = threadIdx.x;
    const int b0 = blockIdx.x * ROWS;

    // Zero both buffers (pads stay 0 forever; h(-1)=0, h2(-2)=0).
    for (int i = t; i < 2 * ROWS * L1_LEN; i += NTHREADS) ((float*)s_in1)[i] = 0.0f;
    for (int i = t; i < 2 * ROWS * L2_LEN; i += NTHREADS) ((float*)s_in2)[i] = 0.0f;

    const bool isL1 = (t < L2_BASE);
    const int  u    = isL1 ? t : (t - L2_BASE);   // [0, 416)
    const int  g    = u >> 3;                     // column-pair group (0..51; 0..49 real)
    const int  s    = u & 7;                      // k-chunk index = final output slot
    const int  gc   = (g < 50) ? g : 49;          // clamped for loads
    const int  c0   = 2 * gc, c1 = 2 * gc + 1;

    // Output assignment after reduce-scatter: lane s of each 8-lane group owns
    // (row = s>>1, col = 2g + (s&1)).
    const int  orow   = s >> 1;
    const int  ocol   = 2 * g + (s & 1);
    const bool ostore = (ocol < H);
    const int  obc    = (ocol < H) ? ocol : (H - 1);

    const float4* __restrict__ xg4 = (const float4*)x;
    const int pre_r = (t >> 4) & 3;   // x-prefetch: 64 threads = 4 rows x 16 float4
    const int pre_d = t & 15;

    // Load weight chunks for both columns into registers.
    float w0[KC2], w1[KC2];
    float biasv;
    if (isL1) {
        const float2* p0 = (const float2*)(g_W1T + c0 * L1_LEN + s * KC1);
        const float2* p1 = (const float2*)(g_W1T + c1 * L1_LEN + s * KC1);
        #pragma unroll
        for (int i = 0; i < KC1 / 2; ++i) {
            float2 a = p0[i]; w0[2 * i] = a.x; w0[2 * i + 1] = a.y;
            float2 b = p1[i]; w1[2 * i] = b.x; w1[2 * i + 1] = b.y;
        }
        biasv = b1[obc];
    } else {
        const float2* p0 = (const float2*)(g_W2T + c0 * L2_LEN + s * KC2);
        const float2* p1 = (const float2*)(g_W2T + c1 * L2_LEN + s * KC2);
        #pragma unroll
        for (int i = 0; i < KC2 / 2; ++i) {
            float2 a = p0[i]; w0[2 * i] = a.x; w0[2 * i + 1] = a.y;
            float2 b = p1[i]; w1[2 * i] = b.x; w1[2 * i + 1] = b.y;
        }
        biasv = b2[obc];
    }

    __syncthreads();   // zero-fill visible before x(0) staging

    // Stage x(0) into buffer 0.
    if (t < 64)
        ((float4*)&s_in1[0][pre_r][0])[pre_d] =
            xg4[(b0 + pre_r) * (T_STEPS * (IN_DIM / 4)) + pre_d];
    __syncthreads();

    // Pipelined phases: at phase p, L1 computes h1(p) (p<T), L2 computes h2(p-1) (p>=1).
    // Reads from buf (p&1), writes to buf (p&1)^1; one barrier per phase.
    for (int p = 0; p <= T_STEPS; ++p) {
        const int pb = p & 1;

        // Prefetch x(p+1) (issued early, stored after compute).
        float4 xpre;
        const bool doPre = isL1 && (t < 64) && (p + 1 < T_STEPS);
        if (doPre)
            xpre = xg4[(b0 + pre_r) * (T_STEPS * (IN_DIM / 4)) + (p + 1) * (IN_DIM / 4) + pre_d];

        float acc[8];   // [row*2 + colsel] partials, k-chunk s only

        if (isL1) {
            if (p < T_STEPS) {
                #pragma unroll
                for (int r = 0; r < ROWS; ++r) {
                    const float2* v = ((const float2*)&s_in1[pb][r][0]) + s * (KC1 / 2);
                    float a0x = 0.0f, a0y = 0.0f, a1x = 0.0f, a1y = 0.0f;
                    #pragma unroll
                    for (int i = 0; i < KC1 / 2; ++i) {
                        float2 vv = v[i];
                        a0x = fmaf(w0[2 * i],     vv.x, a0x);
                        a0y = fmaf(w0[2 * i + 1], vv.y, a0y);
                        a1x = fmaf(w1[2 * i],     vv.x, a1x);
                        a1y = fmaf(w1[2 * i + 1], vv.y, a1y);
                    }
                    acc[r * 2 + 0] = a0x + a0y;
                    acc[r * 2 + 1] = a1x + a1y;
                }
                // Reduce-scatter over the 8 k-split lanes: lane s ends with output s.
                #pragma unroll
                for (int i = 0; i < 4; ++i) {
                    float send = (s & 4) ? acc[i] : acc[i + 4];
                    float keep = (s & 4) ? acc[i + 4] : acc[i];
                    acc[i] = keep + __shfl_xor_sync(0xffffffffu, send, 4);
                }
                #pragma unroll
                for (int i = 0; i < 2; ++i) {
                    float send = (s & 2) ? acc[i] : acc[i + 2];
                    float keep = (s & 2) ? acc[i + 2] : acc[i];
                    acc[i] = keep + __shfl_xor_sync(0xffffffffu, send, 2);
                }
                {
                    float send = (s & 1) ? acc[0] : acc[1];
                    float keep = (s & 1) ? acc[1] : acc[0];
                    float red  = keep + __shfl_xor_sync(0xffffffffu, send, 1);
                    float h = fast_tanh(red + biasv);
                    if (ostore) {
                        s_in1[pb ^ 1][orow][IN_DIM + ocol] = h;   // next L1's h1(t-1)
                        s_in2[pb ^ 1][orow][ocol]          = h;   // next L2's h1(t-1)
                        if (p == T_STEPS - 1)
                            out[NBATCH + (b0 + orow) * H + ocol] = h;   // h1_T
                    }
                }
            }
        } else {
            if (p >= 1) {
                #pragma unroll
                for (int r = 0; r < ROWS; ++r) {
                    const float2* v = ((const float2*)&s_in2[pb][r][0]) + s * (KC2 / 2);
                    float a0x = 0.0f, a0y = 0.0f, a1x = 0.0f, a1y = 0.0f;
                    #pragma unroll
                    for (int i = 0; i < KC2 / 2; ++i) {
                        float2 vv = v[i];
                        a0x = fmaf(w0[2 * i],     vv.x, a0x);
                        a0y = fmaf(w0[2 * i + 1], vv.y, a0y);
                        a1x = fmaf(w1[2 * i],     vv.x, a1x);
                        a1y = fmaf(w1[2 * i + 1], vv.y, a1y);
                    }
                    acc[r * 2 + 0] = a0x + a0y;
                    acc[r * 2 + 1] = a1x + a1y;
                }
                #pragma unroll
                for (int i = 0; i < 4; ++i) {
                    float send = (s & 4) ? acc[i] : acc[i + 4];
                    float keep = (s & 4) ? acc[i + 4] : acc[i];
                    acc[i] = keep + __shfl_xor_sync(0xffffffffu, send, 4);
                }
                #pragma unroll
                for (int i = 0; i < 2; ++i) {
                    float send = (s & 2) ? acc[i] : acc[i + 2];
                    float keep = (s & 2) ? acc[i + 2] : acc[i];
                    acc[i] = keep + __shfl_xor_sync(0xffffffffu, send, 2);
                }
                {
                    float send = (s & 1) ? acc[0] : acc[1];
                    float keep = (s & 1) ? acc[1] : acc[0];
                    float red  = keep + __shfl_xor_sync(0xffffffffu, send, 1);
                    float h = fast_tanh(red + biasv);
                    if (ostore) {
                        s_in2[pb ^ 1][orow][H + ocol] = h;        // next L2's h2(t-1)
                        if (p == T_STEPS)
                            out[NBATCH + NBATCH * H + (b0 + orow) * H + ocol] = h;   // h2_T
                    }
                }
            }
        }

        if (doPre)
            ((float4*)&s_in1[pb ^ 1][pre_r][0])[pre_d] = xpre;

        __syncthreads();
    }

    // out = h2_T @ Wo + bo.  h2(T-1) was written at phase 512 (pb=0) into buffer 1.
    if (t < ROWS) {
        float acc = bo[0];
        #pragma unroll 4
        for (int k = 0; k < H; ++k)
            acc = fmaf(s_in2[1][t][H + k], Wo[k], acc);
        out[b0 + t] = acc;
    }
}

extern "C" void kernel_launch(void* const* d_in, const int* in_sizes, int n_in,
                              void* d_out, int out_size) {
    const float* x   = (const float*)d_in[0];
    const float* W1x = (const float*)d_in[1];
    const float* W1h = (const float*)d_in[2];
    const float* b1  = (const float*)d_in[3];
    const float* W2x = (const float*)d_in[4];
    const float* W2h = (const float*)d_in[5];
    const float* b2  = (const float*)d_in[6];
    const float* Wo  = (const float*)d_in[7];
    const float* bo  = (const float*)d_in[8];
    float* out = (float*)d_out;

    // Build transposed/padded weight images (38400 elements total).
    prep_kernel<<<150, 256>>>(W1x, W1h, W2x, W2h);

    // Persistent batch-partitioned RNN: 128 CTAs x 4 rows, no inter-CTA sync.
    rnn_kernel<<<NCTA, NTHREADS>>>(x, b1, b2, Wo, bo, out);
}

// round 9
// speedup vs baseline: 2.1114x; 1.2828x over previous
#include <cuda_runtime.h>

// Problem constants
#define T_STEPS 512
#define NBATCH  512
#define IN_DIM  64
#define H       100

// Layer-1 input [x(64) | h1(100) | pad(12)] -> 176 floats = 8 chunks of 11 u64
// Layer-2 input [h1(100) | h2(100) | pad(8)] -> 208 floats = 8 chunks of 13 u64
#define L1_LEN  176
#define L2_LEN  208
#define NP1     11      // f32x2 pairs per k-chunk, layer 1
#define NP2     13      // f32x2 pairs per k-chunk, layer 2

#define ROWS     4      // batch rows per CTA
#define NCTA     128    // 128 * 4 = 512 rows
#define NTHREADS 256    // 8 warps: 4 L1 + 4 L2 -> exactly 1 L1 + 1 L2 per SMSP
#define L2_BASE  128
#define CPT      7      // output columns per thread
#define NGRP     16     // groups of 8 lanes per layer; 16*7 = 112 col-slots >= 100

__device__ float g_W1T[H * L1_LEN];   // [col][k] transposed/concat/zero-padded
__device__ float g_W2T[H * L2_LEN];

__global__ void prep_kernel(const float* __restrict__ W1x, const float* __restrict__ W1h,
                            const float* __restrict__ W2x, const float* __restrict__ W2h) {
    int idx = blockIdx.x * blockDim.x + threadIdx.x;
    const int n1 = H * L1_LEN;
    if (idx < n1) {
        int j = idx / L1_LEN, k = idx % L1_LEN;
        float v = 0.0f;
        if (k < IN_DIM)           v = W1x[k * H + j];
        else if (k < IN_DIM + H)  v = W1h[(k - IN_DIM) * H + j];
        g_W1T[idx] = v;
    } else {
        int i2 = idx - n1;
        if (i2 < H * L2_LEN) {
            int j = i2 / L2_LEN, k = i2 % L2_LEN;
            float v = 0.0f;
            if (k < H)            v = W2x[k * H + j];
            else if (k < 2 * H)   v = W2h[(k - H) * H + j];
            g_W2T[i2] = v;
        }
    }
}

// Accurate fast tanh: 1 - 2/(exp(2x)+1).  __expf = MUFU.EX2 path, rel err ~1e-6.
__device__ __forceinline__ float fast_tanh(float x) {
    float e = __expf(2.0f * x);
    return 1.0f - __fdividef(2.0f, e + 1.0f);
}

// Packed fp32 FMA (sm_103a FFMA2): acc = a*b + acc, two k-lanes at once.
__device__ __forceinline__ void ffma2(unsigned long long& acc,
                                      unsigned long long a, unsigned long long b) {
    asm("fma.rn.f32x2 %0, %1, %2, %0;" : "+l"(acc) : "l"(a), "l"(b));
}

__device__ __forceinline__ float hadd2(unsigned long long a) {
    float lo, hi;
    asm("mov.b64 {%0, %1}, %2;" : "=f"(lo), "=f"(hi) : "l"(a));
    return lo + hi;
}

// Accumulate one 2-row batch: A[r2][c] = dot(w[c][chunk s], input row rb+r2)
template<int NP>
__device__ __forceinline__ void accum_batch(
    const float* __restrict__ inbase, int rowlen, int rb, int s,
    const unsigned long long (&w)[CPT][NP2], float (&A)[2][CPT]) {
    #pragma unroll
    for (int r2 = 0; r2 < 2; ++r2) {
        const unsigned long long* v =
            (const unsigned long long*)(inbase + (rb + r2) * rowlen) + s * NP;
        unsigned long long acc[CPT];
        #pragma unroll
        for (int c = 0; c < CPT; ++c) acc[c] = 0ull;
        #pragma unroll
        for (int i = 0; i < NP; ++i) {
            unsigned long long vv = v[i];
            #pragma unroll
            for (int c = 0; c < CPT; ++c) ffma2(acc[c], w[c][i], vv);
        }
        #pragma unroll
        for (int c = 0; c < CPT; ++c) A[r2][c] = hadd2(acc[c]);
    }
}

// Reduce-scatter 7 partials over the 8 k-split lanes, 2 rows interleaved for ILP.
// Result: lane s ends with the full sum for column (7g + s); s == 7 gets a dummy.
__device__ __forceinline__ void reduce7(float (&A)[2][CPT], int s, float (&D)[2]) {
    const bool h4 = (s & 4), h2 = (s & 2), h1 = (s & 1);
    float B[2][4];
    #pragma unroll
    for (int r2 = 0; r2 < 2; ++r2) {
        #pragma unroll
        for (int k = 0; k < 4; ++k) {
            float other = (k < 3) ? A[r2][k + 4] : 0.0f;
            float send = h4 ? A[r2][k] : other;
            float keep = h4 ? other : A[r2][k];
            B[r2][k] = keep + __shfl_xor_sync(0xffffffffu, send, 4);
        }
    }
    float Cv[2][2];
    #pragma unroll
    for (int r2 = 0; r2 < 2; ++r2) {
        #pragma unroll
        for (int k = 0; k < 2; ++k) {
            float send = h2 ? B[r2][k] : B[r2][k + 2];
            float keep = h2 ? B[r2][k + 2] : B[r2][k];
            Cv[r2][k] = keep + __shfl_xor_sync(0xffffffffu, send, 2);
        }
    }
    #pragma unroll
    for (int r2 = 0; r2 < 2; ++r2) {
        float send = h1 ? Cv[r2][0] : Cv[r2][1];
        float keep = h1 ? Cv[r2][1] : Cv[r2][0];
        D[r2] = keep + __shfl_xor_sync(0xffffffffu, send, 1);
    }
}

__global__ void __launch_bounds__(NTHREADS, 1)
rnn_kernel(const float* __restrict__ x,
           const float* __restrict__ b1, const float* __restrict__ b2,
           const float* __restrict__ Wo, const float* __restrict__ bo,
           float* __restrict__ out) {
    __shared__ __align__(16) float s_in1[2][ROWS][L1_LEN];
    __shared__ __align__(16) float s_in2[2][ROWS][L2_LEN];

    const int t  = threadIdx.x;
    const int b0 = blockIdx.x * ROWS;

    for (int i = t; i < 2 * ROWS * L1_LEN; i += NTHREADS) ((float*)s_in1)[i] = 0.0f;
    for (int i = t; i < 2 * ROWS * L2_LEN; i += NTHREADS) ((float*)s_in2)[i] = 0.0f;

    const bool isL1 = (t < L2_BASE);
    const int  u  = isL1 ? t : (t - L2_BASE);   // [0, 128)
    const int  g  = u >> 3;                     // group (0..15)
    const int  s  = u & 7;                      // k-chunk lane = final column-within-group

    const int  ocol_raw = CPT * g + s;
    const bool ostore   = (s < CPT) && (ocol_raw < H);
    const int  ocol     = ostore ? ocol_raw : (H - 1);

    // Weights for 7 columns x one k-chunk, as f32x2 pairs (L2 worst: 91 u64 = 182 regs).
    unsigned long long w[CPT][NP2];
    float biasv;
    if (isL1) {
        #pragma unroll
        for (int c = 0; c < CPT; ++c) {
            int col = CPT * g + c; if (col >= H) col = H - 1;
            const unsigned long long* p =
                (const unsigned long long*)(g_W1T + col * L1_LEN) + s * NP1;
            #pragma unroll
            for (int i = 0; i < NP1; ++i) w[c][i] = p[i];
        }
        biasv = b1[ocol];
    } else {
        #pragma unroll
        for (int c = 0; c < CPT; ++c) {
            int col = CPT * g + c; if (col >= H) col = H - 1;
            const unsigned long long* p =
                (const unsigned long long*)(g_W2T + col * L2_LEN) + s * NP2;
            #pragma unroll
            for (int i = 0; i < NP2; ++i) w[c][i] = p[i];
        }
        biasv = b2[ocol];
    }

    const float4* __restrict__ xg4 = (const float4*)x;
    const int pre_r = (t >> 4) & 3;   // x-prefetch: 64 threads = 4 rows x 16 float4
    const int pre_d = t & 15;

    __syncthreads();   // zero-fill visible before x(0) staging
    if (t < 64)
        ((float4*)&s_in1[0][pre_r][0])[pre_d] =
            xg4[(b0 + pre_r) * (T_STEPS * (IN_DIM / 4)) + pre_d];
    __syncthreads();

    // Pipelined phases: phase p, L1 computes h1(p) (p<T), L2 computes h2(p-1) (p>=1).
    for (int p = 0; p <= T_STEPS; ++p) {
        const int pb = p & 1;

        float4 xpre;
        const bool doPre = isL1 && (t < 64) && (p + 1 < T_STEPS);
        if (doPre)
            xpre = xg4[(b0 + pre_r) * (T_STEPS * (IN_DIM / 4)) + (p + 1) * (IN_DIM / 4) + pre_d];

        if (isL1) {
            if (p < T_STEPS) {
                #pragma unroll
                for (int rb = 0; rb < ROWS; rb += 2) {
                    float A[2][CPT], D[2];
                    accum_batch<NP1>(&s_in1[pb][0][0], L1_LEN, rb, s, w, A);
                    reduce7(A, s, D);
                    #pragma unroll
                    for (int r2 = 0; r2 < 2; ++r2) {
                        float h = fast_tanh(D[r2] + biasv);
                        if (ostore) {
                            int r = rb + r2;
                            s_in1[pb ^ 1][r][IN_DIM + ocol] = h;   // next L1's h1(t-1)
                            s_in2[pb ^ 1][r][ocol]          = h;   // next L2's h1(t-1)
                            if (p == T_STEPS - 1)
                                out[NBATCH + (b0 + r) * H + ocol] = h;   // h1_T
                        }
                    }
                }
            }
        } else {
            if (p >= 1) {
                #pragma unroll
                for (int rb = 0; rb < ROWS; rb += 2) {
                    float A[2][CPT], D[2];
                    accum_batch<NP2>(&s_in2[pb][0][0], L2_LEN, rb, s, w, A);
                    reduce7(A, s, D);
                    #pragma unroll
                    for (int r2 = 0; r2 < 2; ++r2) {
                        float h = fast_tanh(D[r2] + biasv);
                        if (ostore) {
                            int r = rb + r2;
                            s_in2[pb ^ 1][r][H + ocol] = h;        // next L2's h2(t-1)
                            if (p == T_STEPS)
                                out[NBATCH + NBATCH * H + (b0 + r) * H + ocol] = h;  // h2_T
                        }
                    }
                }
            }
        }

        if (doPre)
            ((float4*)&s_in1[pb ^ 1][pre_r][0])[pre_d] = xpre;

        __syncthreads();
    }

    // out = h2_T @ Wo + bo.  h2(T-1) was written at phase 512 (pb=0) into buffer 1.
    if (t < ROWS) {
        float acc = bo[0];
        #pragma unroll 4
        for (int k = 0; k < H; ++k)
            acc = fmaf(s_in2[1][t][H + k], Wo[k], acc);
        out[b0 + t] = acc;
    }
}

extern "C" void kernel_launch(void* const* d_in, const int* in_sizes, int n_in,
                              void* d_out, int out_size) {
    const float* x   = (const float*)d_in[0];
    const float* W1x = (const float*)d_in[1];
    const float* W1h = (const float*)d_in[2];
    const float* b1  = (const float*)d_in[3];
    const float* W2x = (const float*)d_in[4];
    const float* W2h = (const float*)d_in[5];
    const float* b2  = (const float*)d_in[6];
    const float* Wo  = (const float*)d_in[7];
    const float* bo  = (const float*)d_in[8];
    float* out = (float*)d_out;

    // Build transposed/padded weight images (38400 elements total).
    prep_kernel<<<150, 256>>>(W1x, W1h, W2x, W2h);

    // Persistent batch-partitioned RNN: 128 CTAs x 4 rows, no inter-CTA sync.
    rnn_kernel<<<NCTA, NTHREADS>>>(x, b1, b2, Wo, bo, out);
}